// round 1
// baseline (speedup 1.0000x reference)
#include <cuda_runtime.h>
#include <math.h>

#define EDIM 1024
#define NH   16
#define HD   64
#define NB   2
#define LQ   2048
#define SK   2048

// Scratch (device globals are the allocation-rule-safe scratch path)
__device__ float g_q[NB * LQ * EDIM];     // 16 MB
__device__ float g_k[NB * SK * EDIM];     // 16 MB
__device__ float g_v[NB * SK * EDIM];     // 16 MB
__device__ float g_attn[NB * LQ * EDIM];  // 16 MB

// ---------------------------------------------------------------------------
// NT GEMM: C[M,N] = alpha * A[M,K] * B[N,K]^T (+ bias[N])
// 128x128 block tile, BK=8, 256 threads, 8x8 microtile per thread.
// Grid exactly covers M,N (all dims multiples of 128); batched via blockIdx.z
// with (z/hdiv, z%hdiv) offset decomposition for (batch, head) addressing.
// ---------------------------------------------------------------------------
__global__ __launch_bounds__(256, 2) void gemm_nt(
    const float* __restrict__ A, const float* __restrict__ B,
    float* __restrict__ C, const float* __restrict__ bias,
    int K, int lda, int ldb, long long ldc, float alpha,
    int hdiv,
    long long aOut, long long aIn,
    long long bOut, long long bIn,
    long long cOut, long long cIn)
{
    int z  = blockIdx.z;
    int zo = z / hdiv;
    int zi = z - zo * hdiv;
    const float* Az = A + zo * aOut + zi * aIn + (long long)(blockIdx.y * 128) * lda;
    const float* Bz = B + zo * bOut + zi * bIn + (long long)(blockIdx.x * 128) * ldb;
    float*       Cz = C + zo * cOut + zi * cIn;

    __shared__ float As[8][128];
    __shared__ float Bs[8][128];

    int tid = threadIdx.x;
    int ar  = tid >> 1;          // 0..127
    int ac  = (tid & 1) << 2;    // 0 or 4
    int ty  = tid >> 4;          // 0..15
    int tx  = tid & 15;          // 0..15

    float acc[8][8] = {};

    const float* aptr = Az + (long long)ar * lda + ac;
    const float* bptr = Bz + (long long)ar * ldb + ac;

    for (int k0 = 0; k0 < K; k0 += 8) {
        float4 av = *(const float4*)(aptr + k0);
        float4 bv = *(const float4*)(bptr + k0);
        As[ac + 0][ar] = av.x; As[ac + 1][ar] = av.y;
        As[ac + 2][ar] = av.z; As[ac + 3][ar] = av.w;
        Bs[ac + 0][ar] = bv.x; Bs[ac + 1][ar] = bv.y;
        Bs[ac + 2][ar] = bv.z; Bs[ac + 3][ar] = bv.w;
        __syncthreads();
        #pragma unroll
        for (int kk = 0; kk < 8; kk++) {
            float a[8], b[8];
            #pragma unroll
            for (int i = 0; i < 8; i++) a[i] = As[kk][ty * 8 + i];
            #pragma unroll
            for (int j = 0; j < 8; j++) b[j] = Bs[kk][tx * 8 + j];
            #pragma unroll
            for (int i = 0; i < 8; i++)
                #pragma unroll
                for (int j = 0; j < 8; j++)
                    acc[i][j] = fmaf(a[i], b[j], acc[i][j]);
        }
        __syncthreads();
    }

    int row0 = blockIdx.y * 128 + ty * 8;
    int col0 = blockIdx.x * 128 + tx * 8;
    #pragma unroll
    for (int i = 0; i < 8; i++) {
        #pragma unroll
        for (int j = 0; j < 8; j++) {
            float v = acc[i][j] * alpha;
            if (bias) v += bias[col0 + j];
            Cz[(long long)(row0 + i) * ldc + (col0 + j)] = v;
        }
    }
}

// ---------------------------------------------------------------------------
// NN GEMM (for P @ V): C[M,64] = A[M,K] * B[K,64]
// 128x64 block tile, BK=8, 256 threads, 8x4 microtile.
// ---------------------------------------------------------------------------
__global__ __launch_bounds__(256, 2) void gemm_nn(
    const float* __restrict__ A, const float* __restrict__ B,
    float* __restrict__ C,
    int K, long long lda, int ldb, int ldc,
    int hdiv,
    long long aOut, long long aIn,
    long long bOut, long long bIn,
    long long cOut, long long cIn)
{
    int z  = blockIdx.z;
    int zo = z / hdiv;
    int zi = z - zo * hdiv;
    const float* Az = A + zo * aOut + zi * aIn + (long long)(blockIdx.y * 128) * lda;
    const float* Bz = B + zo * bOut + zi * bIn;
    float*       Cz = C + zo * cOut + zi * cIn;

    __shared__ float As[8][128];
    __shared__ float Bs[8][64];

    int tid = threadIdx.x;
    int ar  = tid >> 1;          // 0..127
    int ac  = (tid & 1) << 2;    // 0 or 4
    int br  = tid >> 5;          // 0..7
    int bc  = (tid & 31) << 1;   // 0..62
    int ty  = tid >> 4;          // 0..15
    int tx  = tid & 15;          // 0..15

    float acc[8][4] = {};

    for (int k0 = 0; k0 < K; k0 += 8) {
        float4 av = *(const float4*)(Az + (long long)ar * lda + k0 + ac);
        float2 bv = *(const float2*)(Bz + (long long)(k0 + br) * ldb + bc);
        As[ac + 0][ar] = av.x; As[ac + 1][ar] = av.y;
        As[ac + 2][ar] = av.z; As[ac + 3][ar] = av.w;
        Bs[br][bc] = bv.x; Bs[br][bc + 1] = bv.y;
        __syncthreads();
        #pragma unroll
        for (int kk = 0; kk < 8; kk++) {
            float a[8], b[4];
            #pragma unroll
            for (int i = 0; i < 8; i++) a[i] = As[kk][ty * 8 + i];
            #pragma unroll
            for (int j = 0; j < 4; j++) b[j] = Bs[kk][tx * 4 + j];
            #pragma unroll
            for (int i = 0; i < 8; i++)
                #pragma unroll
                for (int j = 0; j < 4; j++)
                    acc[i][j] = fmaf(a[i], b[j], acc[i][j]);
        }
        __syncthreads();
    }

    int row0 = blockIdx.y * 128 + ty * 8;
    int col0 = tx * 4;
    #pragma unroll
    for (int i = 0; i < 8; i++)
        #pragma unroll
        for (int j = 0; j < 4; j++)
            Cz[(long long)(row0 + i) * ldc + (col0 + j)] = acc[i][j];
}

// ---------------------------------------------------------------------------
// Fused stable softmax + L1 renormalize, in place. One block per row of 2048.
// Row lives in 8 registers/thread (256 threads).
// ---------------------------------------------------------------------------
__global__ __launch_bounds__(256) void softmax_l1(float* __restrict__ W)
{
    float* p = W + (long long)blockIdx.x * SK;
    int tid  = threadIdx.x;
    __shared__ float sh[8];

    float v[8];
    float m = -3.402823466e38f;
    #pragma unroll
    for (int i = 0; i < 8; i++) {
        v[i] = p[i * 256 + tid];
        m = fmaxf(m, v[i]);
    }
    // block max
    #pragma unroll
    for (int o = 16; o; o >>= 1) m = fmaxf(m, __shfl_xor_sync(0xffffffffu, m, o));
    if ((tid & 31) == 0) sh[tid >> 5] = m;
    __syncthreads();
    m = sh[0];
    #pragma unroll
    for (int i = 1; i < 8; i++) m = fmaxf(m, sh[i]);
    __syncthreads();

    float s = 0.0f;
    #pragma unroll
    for (int i = 0; i < 8; i++) {
        v[i] = expf(v[i] - m);
        s += v[i];
    }
    // block sum (denom)
    #pragma unroll
    for (int o = 16; o; o >>= 1) s += __shfl_xor_sync(0xffffffffu, s, o);
    if ((tid & 31) == 0) sh[tid >> 5] = s;
    __syncthreads();
    float denom = 0.0f;
    #pragma unroll
    for (int i = 0; i < 8; i++) denom += sh[i];
    __syncthreads();
    denom = (denom > 0.0f) ? denom : 1.0f;
    float inv = 1.0f / denom;

    float s2 = 0.0f;
    #pragma unroll
    for (int i = 0; i < 8; i++) {
        v[i] *= inv;
        s2 += v[i];
    }
    // block sum (L1 norm of w; w >= 0)
    #pragma unroll
    for (int o = 16; o; o >>= 1) s2 += __shfl_xor_sync(0xffffffffu, s2, o);
    if ((tid & 31) == 0) sh[tid >> 5] = s2;
    __syncthreads();
    float l1 = 0.0f;
    #pragma unroll
    for (int i = 0; i < 8; i++) l1 += sh[i];
    float inv2 = 1.0f / fmaxf(l1, 1e-12f);

    #pragma unroll
    for (int i = 0; i < 8; i++) p[i * 256 + tid] = v[i] * inv2;
}

// ---------------------------------------------------------------------------
extern "C" void kernel_launch(void* const* d_in, const int* in_sizes, int n_in,
                              void* d_out, int out_size)
{
    const float* query = (const float*)d_in[0];
    const float* key   = (const float*)d_in[1];
    const float* value = (const float*)d_in[2];
    const float* Wq    = (const float*)d_in[3];
    const float* bq    = (const float*)d_in[4];
    const float* Wk    = (const float*)d_in[5];
    const float* bk    = (const float*)d_in[6];
    const float* Wv    = (const float*)d_in[7];
    const float* bv    = (const float*)d_in[8];
    const float* Wo    = (const float*)d_in[9];
    const float* bo    = (const float*)d_in[10];

    float* out = (float*)d_out;                              // (N, L, E)
    float* w   = out + (long long)NB * LQ * EDIM;            // (N, H, L, S)

    float *pq, *pk, *pv, *pa;
    cudaGetSymbolAddress((void**)&pq, g_q);
    cudaGetSymbolAddress((void**)&pk, g_k);
    cudaGetSymbolAddress((void**)&pv, g_v);
    cudaGetSymbolAddress((void**)&pa, g_attn);

    const float scaling = 0.125f;  // 64^-0.5
    dim3 blk(256);

    // Q/K/V projections: [4096,1024] = X[4096,1024] @ W[1024,1024]^T + b
    dim3 gproj(EDIM / 128, (NB * LQ) / 128, 1);
    gemm_nt<<<gproj, blk>>>(query, Wq, pq, bq, EDIM, EDIM, EDIM, EDIM, 1.0f,
                            1, 0, 0, 0, 0, 0, 0);
    gemm_nt<<<gproj, blk>>>(key,   Wk, pk, bk, EDIM, EDIM, EDIM, EDIM, 1.0f,
                            1, 0, 0, 0, 0, 0, 0);
    gemm_nt<<<gproj, blk>>>(value, Wv, pv, bv, EDIM, EDIM, EDIM, EDIM, 1.0f,
                            1, 0, 0, 0, 0, 0, 0);

    // scores: per (n,h): w[l,s] = scale * Q_h[l,:] . K_h[s,:]   (K=64)
    dim3 gsc(SK / 128, LQ / 128, NB * NH);
    gemm_nt<<<gsc, blk>>>(pq, pk, w, nullptr, HD, EDIM, EDIM, (long long)SK,
                          scaling, NH,
                          (long long)LQ * EDIM, HD,
                          (long long)SK * EDIM, HD,
                          (long long)NH * LQ * SK, (long long)LQ * SK);

    // softmax + L1 renorm over each row of w (in place, in d_out)
    softmax_l1<<<NB * NH * LQ, blk>>>(w);

    // attn_out: per (n,h): A[l,d] = w[l,:] @ V_h[:,d]  -> (N,L,E) layout
    dim3 gav(1, LQ / 128, NB * NH);
    gemm_nn<<<gav, blk>>>(w, pv, pa, SK, (long long)SK, EDIM, EDIM,
                          NH,
                          (long long)NH * LQ * SK, (long long)LQ * SK,
                          (long long)SK * EDIM, HD,
                          (long long)LQ * EDIM, HD);

    // output projection: out = attn @ Wo^T + bo
    gemm_nt<<<gproj, blk>>>(pa, Wo, out, bo, EDIM, EDIM, EDIM, EDIM, 1.0f,
                            1, 0, 0, 0, 0, 0, 0);
}

// round 4
// speedup vs baseline: 4.0466x; 4.0466x over previous
#include <cuda_runtime.h>
#include <cstdint>
#include <math.h>

#define EDIM 1024
#define NH   16
#define HD   64
#define NB   2
#define LQ   2048
#define SK   2048

// Scratch (device globals = allocation-rule-safe scratch)
__device__ float g_q[NB * LQ * EDIM];       // Q projected (N,L,E)
__device__ float g_k[NB * SK * EDIM];       // K projected (N,S,E)
__device__ float g_vT[NB * NH * HD * SK];   // V projected, transposed (N,H,D,S)
__device__ float g_attn[NB * LQ * EDIM];    // attn out (N,L,E)

__device__ __forceinline__ uint32_t f2tf32(float f) {
    uint32_t u;
    asm("cvt.rna.tf32.f32 %0, %1;" : "=r"(u) : "f"(f));
    return u;
}

__device__ __forceinline__ void mma_tf32(float* c, const uint32_t* a, const uint32_t* b) {
    asm volatile(
        "mma.sync.aligned.m16n8k8.row.col.f32.tf32.tf32.f32 "
        "{%0,%1,%2,%3}, {%4,%5,%6,%7}, {%8,%9}, {%0,%1,%2,%3};"
        : "+f"(c[0]), "+f"(c[1]), "+f"(c[2]), "+f"(c[3])
        : "r"(a[0]), "r"(a[1]), "r"(a[2]), "r"(a[3]), "r"(b[0]), "r"(b[1]));
}

// ---------------------------------------------------------------------------
// TF32 mma.sync NT GEMM: C[M,N] = alpha * A[M,K] @ B[N,K]^T (+ bias[N])
// CTA tile 128 x BN, BK=16, 256 threads (8 warps), double-buffered SMEM.
// TSTORE: write V-projection output transposed into (N,H,D,S) layout.
// Batched via blockIdx.z with (z/hdiv, z%hdiv) offset decomposition.
// ---------------------------------------------------------------------------
template <int BN, bool TSTORE>
__global__ __launch_bounds__(256, 2)
void gemm_mma(const float* __restrict__ A, const float* __restrict__ B,
              float* __restrict__ C, const float* __restrict__ bias,
              int K, int lda, int ldb, long long ldc, float alpha, int hdiv,
              long long aOut, long long aIn,
              long long bOut, long long bIn,
              long long cOut, long long cIn)
{
    constexpr int WM  = (BN == 128) ? 2 : 4;   // warps along M
    constexpr int FM  = 8 / WM;                // 16-row m-frags per warp
    constexpr int NB4 = BN / 64;               // B staging float4s per thread

    __shared__ float As[2][128][20];
    __shared__ float Bs[2][BN][20];

    const int tid  = threadIdx.x;
    const int wid  = tid >> 5;
    const int lane = tid & 31;
    const int g    = lane >> 2;    // group id (0..7)
    const int tg   = lane & 3;     // thread-in-group (0..3)
    const int wm   = wid % WM;
    const int wn   = wid / WM;
    const int mBase = wm * (128 / WM);
    const int nBase = wn * 32;

    const int z  = blockIdx.z;
    const int zo = z / hdiv;
    const int zi = z - zo * hdiv;
    const float* Az = A + zo * aOut + zi * aIn + (long long)(blockIdx.y * 128) * lda;
    const float* Bz = B + zo * bOut + zi * bIn + (long long)(blockIdx.x * BN) * ldb;

    const int T = K >> 4;

    uint32_t ra[2][4], rb[NB4][4];

    // ---- prologue: load tile 0 straight to SMEM buffer 0 ----
    {
        #pragma unroll
        for (int i = 0; i < 2; i++) {
            int idx = i * 256 + tid;
            int r = idx >> 2, c = (idx & 3) << 2;
            float4 v = *(const float4*)(Az + (long long)r * lda + c);
            As[0][r][c + 0] = __uint_as_float(f2tf32(v.x));
            As[0][r][c + 1] = __uint_as_float(f2tf32(v.y));
            As[0][r][c + 2] = __uint_as_float(f2tf32(v.z));
            As[0][r][c + 3] = __uint_as_float(f2tf32(v.w));
        }
        #pragma unroll
        for (int i = 0; i < NB4; i++) {
            int idx = i * 256 + tid;
            int r = idx >> 2, c = (idx & 3) << 2;
            float4 v = *(const float4*)(Bz + (long long)r * ldb + c);
            Bs[0][r][c + 0] = __uint_as_float(f2tf32(v.x));
            Bs[0][r][c + 1] = __uint_as_float(f2tf32(v.y));
            Bs[0][r][c + 2] = __uint_as_float(f2tf32(v.z));
            Bs[0][r][c + 3] = __uint_as_float(f2tf32(v.w));
        }
    }
    __syncthreads();

    float acc[FM][4][4] = {};
    int cur = 0;

    for (int t = 0; t < T; t++) {
        // stage next tile into registers
        if (t + 1 < T) {
            const int k0 = (t + 1) << 4;
            #pragma unroll
            for (int i = 0; i < 2; i++) {
                int idx = i * 256 + tid;
                int r = idx >> 2, c = (idx & 3) << 2;
                float4 v = *(const float4*)(Az + (long long)r * lda + k0 + c);
                ra[i][0] = f2tf32(v.x); ra[i][1] = f2tf32(v.y);
                ra[i][2] = f2tf32(v.z); ra[i][3] = f2tf32(v.w);
            }
            #pragma unroll
            for (int i = 0; i < NB4; i++) {
                int idx = i * 256 + tid;
                int r = idx >> 2, c = (idx & 3) << 2;
                float4 v = *(const float4*)(Bz + (long long)r * ldb + k0 + c);
                rb[i][0] = f2tf32(v.x); rb[i][1] = f2tf32(v.y);
                rb[i][2] = f2tf32(v.z); rb[i][3] = f2tf32(v.w);
            }
        }

        // compute on current buffer: 2 k-steps of 8
        #pragma unroll
        for (int ks = 0; ks < 2; ks++) {
            const int kk = ks * 8;
            uint32_t af[FM][4];
            #pragma unroll
            for (int fm = 0; fm < FM; fm++) {
                const int r = mBase + fm * 16 + g;
                af[fm][0] = __float_as_uint(As[cur][r    ][kk + tg]);
                af[fm][1] = __float_as_uint(As[cur][r + 8][kk + tg]);
                af[fm][2] = __float_as_uint(As[cur][r    ][kk + tg + 4]);
                af[fm][3] = __float_as_uint(As[cur][r + 8][kk + tg + 4]);
            }
            uint32_t bf[4][2];
            #pragma unroll
            for (int fn = 0; fn < 4; fn++) {
                const int r = nBase + fn * 8 + g;
                bf[fn][0] = __float_as_uint(Bs[cur][r][kk + tg]);
                bf[fn][1] = __float_as_uint(Bs[cur][r][kk + tg + 4]);
            }
            #pragma unroll
            for (int fm = 0; fm < FM; fm++)
                #pragma unroll
                for (int fn = 0; fn < 4; fn++)
                    mma_tf32(acc[fm][fn], af[fm], bf[fn]);
        }

        // publish staged tile to the other buffer
        if (t + 1 < T) {
            const int nxt = cur ^ 1;
            #pragma unroll
            for (int i = 0; i < 2; i++) {
                int idx = i * 256 + tid;
                int r = idx >> 2, c = (idx & 3) << 2;
                As[nxt][r][c + 0] = __uint_as_float(ra[i][0]);
                As[nxt][r][c + 1] = __uint_as_float(ra[i][1]);
                As[nxt][r][c + 2] = __uint_as_float(ra[i][2]);
                As[nxt][r][c + 3] = __uint_as_float(ra[i][3]);
            }
            #pragma unroll
            for (int i = 0; i < NB4; i++) {
                int idx = i * 256 + tid;
                int r = idx >> 2, c = (idx & 3) << 2;
                Bs[nxt][r][c + 0] = __uint_as_float(rb[i][0]);
                Bs[nxt][r][c + 1] = __uint_as_float(rb[i][1]);
                Bs[nxt][r][c + 2] = __uint_as_float(rb[i][2]);
                Bs[nxt][r][c + 3] = __uint_as_float(rb[i][3]);
            }
            __syncthreads();
            cur = nxt;
        }
    }

    // ---- epilogue ----
    const int rowBlk = blockIdx.y * 128;
    const int colBlk = blockIdx.x * BN;
    #pragma unroll
    for (int fm = 0; fm < FM; fm++) {
        const int r0 = rowBlk + mBase + fm * 16 + g;
        const int r1 = r0 + 8;
        #pragma unroll
        for (int fn = 0; fn < 4; fn++) {
            const int col = colBlk + nBase + fn * 8 + tg * 2;
            float c0 = acc[fm][fn][0] * alpha;
            float c1 = acc[fm][fn][1] * alpha;
            float c2 = acc[fm][fn][2] * alpha;
            float c3 = acc[fm][fn][3] * alpha;
            if (bias) {
                float b0 = bias[col], b1 = bias[col + 1];
                c0 += b0; c1 += b1; c2 += b0; c3 += b1;
            }
            if (!TSTORE) {
                float* Cz = C + zo * cOut + zi * cIn;
                *(float2*)(Cz + (long long)r0 * ldc + col) = make_float2(c0, c1);
                *(float2*)(Cz + (long long)r1 * ldc + col) = make_float2(c2, c3);
            } else {
                // V transposed store: row=(n,s), col=(h*64+d) -> Vt[n][col][s]
                const long long n0 = r0 >> 11; const int s0 = r0 & 2047;
                const long long n1 = r1 >> 11; const int s1 = r1 & 2047;
                C[n0 * 2097152LL + (long long)(col    ) * 2048 + s0] = c0;
                C[n0 * 2097152LL + (long long)(col + 1) * 2048 + s0] = c1;
                C[n1 * 2097152LL + (long long)(col    ) * 2048 + s1] = c2;
                C[n1 * 2097152LL + (long long)(col + 1) * 2048 + s1] = c3;
            }
        }
    }
}

// ---------------------------------------------------------------------------
// Fused stable softmax + L1 renormalize, in place. One block per row of 2048.
// ---------------------------------------------------------------------------
__global__ __launch_bounds__(256) void softmax_l1(float* __restrict__ W)
{
    float* p = W + (long long)blockIdx.x * SK;
    int tid = threadIdx.x;
    __shared__ float sh[8];

    float v[8];
    float m = -3.402823466e38f;
    #pragma unroll
    for (int i = 0; i < 8; i++) { v[i] = p[i * 256 + tid]; m = fmaxf(m, v[i]); }
    #pragma unroll
    for (int o = 16; o; o >>= 1) m = fmaxf(m, __shfl_xor_sync(0xffffffffu, m, o));
    if ((tid & 31) == 0) sh[tid >> 5] = m;
    __syncthreads();
    m = sh[0];
    #pragma unroll
    for (int i = 1; i < 8; i++) m = fmaxf(m, sh[i]);
    __syncthreads();

    float s = 0.0f;
    #pragma unroll
    for (int i = 0; i < 8; i++) { v[i] = expf(v[i] - m); s += v[i]; }
    #pragma unroll
    for (int o = 16; o; o >>= 1) s += __shfl_xor_sync(0xffffffffu, s, o);
    if ((tid & 31) == 0) sh[tid >> 5] = s;
    __syncthreads();
    float denom = 0.0f;
    #pragma unroll
    for (int i = 0; i < 8; i++) denom += sh[i];
    __syncthreads();
    denom = (denom > 0.0f) ? denom : 1.0f;
    float inv = 1.0f / denom;

    float s2 = 0.0f;
    #pragma unroll
    for (int i = 0; i < 8; i++) { v[i] *= inv; s2 += v[i]; }
    #pragma unroll
    for (int o = 16; o; o >>= 1) s2 += __shfl_xor_sync(0xffffffffu, s2, o);
    if ((tid & 31) == 0) sh[tid >> 5] = s2;
    __syncthreads();
    float l1 = 0.0f;
    #pragma unroll
    for (int i = 0; i < 8; i++) l1 += sh[i];
    float inv2 = 1.0f / fmaxf(l1, 1e-12f);

    #pragma unroll
    for (int i = 0; i < 8; i++) p[i * 256 + tid] = v[i] * inv2;
}

// ---------------------------------------------------------------------------
extern "C" void kernel_launch(void* const* d_in, const int* in_sizes, int n_in,
                              void* d_out, int out_size)
{
    const float* query = (const float*)d_in[0];
    const float* key   = (const float*)d_in[1];
    const float* value = (const float*)d_in[2];
    const float* Wq    = (const float*)d_in[3];
    const float* bq    = (const float*)d_in[4];
    const float* Wk    = (const float*)d_in[5];
    const float* bk    = (const float*)d_in[6];
    const float* Wv    = (const float*)d_in[7];
    const float* bv    = (const float*)d_in[8];
    const float* Wo    = (const float*)d_in[9];
    const float* bo    = (const float*)d_in[10];

    float* out = (float*)d_out;                   // (N, L, E)
    float* w   = out + (long long)NB * LQ * EDIM; // (N, H, L, S)

    float *pq, *pk, *pvT, *pa;
    cudaGetSymbolAddress((void**)&pq, g_q);
    cudaGetSymbolAddress((void**)&pk, g_k);
    cudaGetSymbolAddress((void**)&pvT, g_vT);
    cudaGetSymbolAddress((void**)&pa, g_attn);

    dim3 blk(256);
    dim3 gproj(EDIM / 128, (NB * LQ) / 128, 1);

    // Q/K projections (NT GEMM), V projection with transposed store
    gemm_mma<128, false><<<gproj, blk>>>(
        query, Wq, pq, bq, EDIM, EDIM, EDIM, EDIM, 1.0f, 1, 0, 0, 0, 0, 0, 0);
    gemm_mma<128, false><<<gproj, blk>>>(
        key, Wk, pk, bk, EDIM, EDIM, EDIM, EDIM, 1.0f, 1, 0, 0, 0, 0, 0, 0);
    gemm_mma<128, true><<<gproj, blk>>>(
        value, Wv, pvT, bv, EDIM, EDIM, EDIM, 0, 1.0f, 1, 0, 0, 0, 0, 0, 0);

    // scores: per (n,h): w[l,s] = 0.125 * Q_h[l,:] . K_h[s,:]  (K=64)
    dim3 gsc(SK / 128, LQ / 128, NB * NH);
    gemm_mma<128, false><<<gsc, blk>>>(
        pq, pk, w, nullptr, HD, EDIM, EDIM, (long long)SK, 0.125f, NH,
        (long long)LQ * EDIM, HD,
        (long long)SK * EDIM, HD,
        (long long)NH * LQ * SK, (long long)LQ * SK);

    // softmax + L1 renorm in place
    softmax_l1<<<NB * NH * LQ, 256>>>(w);

    // attn: per (n,h): A[l,d] = w[l,:] . Vt_h[d,:]  (K=2048, N=64)
    dim3 gav(1, LQ / 128, NB * NH);
    gemm_mma<64, false><<<gav, blk>>>(
        w, pvT, pa, nullptr, SK, SK, SK, (long long)EDIM, 1.0f, NH,
        (long long)NH * LQ * SK, (long long)LQ * SK,
        (long long)NH * HD * SK, (long long)HD * SK,
        (long long)LQ * EDIM, (long long)HD);

    // output projection
    gemm_mma<128, false><<<gproj, blk>>>(
        pa, Wo, out, bo, EDIM, EDIM, EDIM, EDIM, 1.0f, 1, 0, 0, 0, 0, 0, 0);
}

// round 7
// speedup vs baseline: 4.1681x; 1.0300x over previous
#include <cuda_runtime.h>
#include <cstdint>
#include <math.h>

#define EDIM 1024
#define NH   16
#define HD   64
#define NB   2
#define LQ   2048
#define SK   2048

// Scratch (device globals = allocation-rule-safe scratch)
__device__ float g_q[NB * LQ * EDIM];       // Q projected (N,L,E)
__device__ float g_k[NB * SK * EDIM];       // K projected (N,S,E)
__device__ float g_vT[NB * NH * HD * SK];   // V projected, transposed (N,H,D,S)
__device__ float g_attn[NB * LQ * EDIM];    // attn out (N,L,E)

__device__ __forceinline__ uint32_t f2tf32(float f) {
    uint32_t u;
    asm("cvt.rna.tf32.f32 %0, %1;" : "=r"(u) : "f"(f));
    return u;
}

__device__ __forceinline__ void mma_tf32(float* c, const uint32_t* a, const uint32_t* b) {
    asm volatile(
        "mma.sync.aligned.m16n8k8.row.col.f32.tf32.tf32.f32 "
        "{%0,%1,%2,%3}, {%4,%5,%6,%7}, {%8,%9}, {%0,%1,%2,%3};"
        : "+f"(c[0]), "+f"(c[1]), "+f"(c[2]), "+f"(c[3])
        : "r"(a[0]), "r"(a[1]), "r"(a[2]), "r"(a[3]), "r"(b[0]), "r"(b[1]));
}

// ---------------------------------------------------------------------------
// TF32 mma.sync NT GEMM: C[M,N] = alpha * A[M,K] @ B[N,K]^T (+ bias[N])
// CTA tile 128 x BN, BK=16, 256 threads (8 warps), double-buffered SMEM.
// TSTORE: write V-projection output transposed into (N,H,D,S) layout.
// ---------------------------------------------------------------------------
template <int BN, bool TSTORE>
__global__ __launch_bounds__(256, 2)
void gemm_mma(const float* __restrict__ A, const float* __restrict__ B,
              float* __restrict__ C, const float* __restrict__ bias,
              int K, int lda, int ldb, long long ldc, float alpha)
{
    constexpr int WM  = 2;                     // warps along M
    constexpr int FM  = 8 / WM;                // 16-row m-frags per warp
    constexpr int NB4 = BN / 64;               // B staging float4s per thread

    __shared__ float As[2][128][20];
    __shared__ float Bs[2][BN][20];

    const int tid  = threadIdx.x;
    const int wid  = tid >> 5;
    const int lane = tid & 31;
    const int g    = lane >> 2;
    const int tg   = lane & 3;
    const int wm   = wid % WM;
    const int wn   = wid / WM;
    const int mBase = wm * (128 / WM);
    const int nBase = wn * 32;

    const float* Az = A + (long long)(blockIdx.y * 128) * lda;
    const float* Bz = B + (long long)(blockIdx.x * BN) * ldb;

    const int T = K >> 4;
    uint32_t ra[2][4], rb[NB4][4];

    {
        #pragma unroll
        for (int i = 0; i < 2; i++) {
            int idx = i * 256 + tid;
            int r = idx >> 2, c = (idx & 3) << 2;
            float4 v = *(const float4*)(Az + (long long)r * lda + c);
            As[0][r][c + 0] = __uint_as_float(f2tf32(v.x));
            As[0][r][c + 1] = __uint_as_float(f2tf32(v.y));
            As[0][r][c + 2] = __uint_as_float(f2tf32(v.z));
            As[0][r][c + 3] = __uint_as_float(f2tf32(v.w));
        }
        #pragma unroll
        for (int i = 0; i < NB4; i++) {
            int idx = i * 256 + tid;
            int r = idx >> 2, c = (idx & 3) << 2;
            float4 v = *(const float4*)(Bz + (long long)r * ldb + c);
            Bs[0][r][c + 0] = __uint_as_float(f2tf32(v.x));
            Bs[0][r][c + 1] = __uint_as_float(f2tf32(v.y));
            Bs[0][r][c + 2] = __uint_as_float(f2tf32(v.z));
            Bs[0][r][c + 3] = __uint_as_float(f2tf32(v.w));
        }
    }
    __syncthreads();

    float acc[FM][4][4] = {};
    int cur = 0;

    for (int t = 0; t < T; t++) {
        if (t + 1 < T) {
            const int k0 = (t + 1) << 4;
            #pragma unroll
            for (int i = 0; i < 2; i++) {
                int idx = i * 256 + tid;
                int r = idx >> 2, c = (idx & 3) << 2;
                float4 v = *(const float4*)(Az + (long long)r * lda + k0 + c);
                ra[i][0] = f2tf32(v.x); ra[i][1] = f2tf32(v.y);
                ra[i][2] = f2tf32(v.z); ra[i][3] = f2tf32(v.w);
            }
            #pragma unroll
            for (int i = 0; i < NB4; i++) {
                int idx = i * 256 + tid;
                int r = idx >> 2, c = (idx & 3) << 2;
                float4 v = *(const float4*)(Bz + (long long)r * ldb + k0 + c);
                rb[i][0] = f2tf32(v.x); rb[i][1] = f2tf32(v.y);
                rb[i][2] = f2tf32(v.z); rb[i][3] = f2tf32(v.w);
            }
        }

        #pragma unroll
        for (int ks = 0; ks < 2; ks++) {
            const int kk = ks * 8;
            uint32_t af[FM][4];
            #pragma unroll
            for (int fm = 0; fm < FM; fm++) {
                const int r = mBase + fm * 16 + g;
                af[fm][0] = __float_as_uint(As[cur][r    ][kk + tg]);
                af[fm][1] = __float_as_uint(As[cur][r + 8][kk + tg]);
                af[fm][2] = __float_as_uint(As[cur][r    ][kk + tg + 4]);
                af[fm][3] = __float_as_uint(As[cur][r + 8][kk + tg + 4]);
            }
            uint32_t bf[4][2];
            #pragma unroll
            for (int fn = 0; fn < 4; fn++) {
                const int r = nBase + fn * 8 + g;
                bf[fn][0] = __float_as_uint(Bs[cur][r][kk + tg]);
                bf[fn][1] = __float_as_uint(Bs[cur][r][kk + tg + 4]);
            }
            #pragma unroll
            for (int fm = 0; fm < FM; fm++)
                #pragma unroll
                for (int fn = 0; fn < 4; fn++)
                    mma_tf32(acc[fm][fn], af[fm], bf[fn]);
        }

        if (t + 1 < T) {
            const int nxt = cur ^ 1;
            #pragma unroll
            for (int i = 0; i < 2; i++) {
                int idx = i * 256 + tid;
                int r = idx >> 2, c = (idx & 3) << 2;
                As[nxt][r][c + 0] = __uint_as_float(ra[i][0]);
                As[nxt][r][c + 1] = __uint_as_float(ra[i][1]);
                As[nxt][r][c + 2] = __uint_as_float(ra[i][2]);
                As[nxt][r][c + 3] = __uint_as_float(ra[i][3]);
            }
            #pragma unroll
            for (int i = 0; i < NB4; i++) {
                int idx = i * 256 + tid;
                int r = idx >> 2, c = (idx & 3) << 2;
                Bs[nxt][r][c + 0] = __uint_as_float(rb[i][0]);
                Bs[nxt][r][c + 1] = __uint_as_float(rb[i][1]);
                Bs[nxt][r][c + 2] = __uint_as_float(rb[i][2]);
                Bs[nxt][r][c + 3] = __uint_as_float(rb[i][3]);
            }
            __syncthreads();
            cur = nxt;
        }
    }

    const int rowBlk = blockIdx.y * 128;
    const int colBlk = blockIdx.x * BN;
    #pragma unroll
    for (int fm = 0; fm < FM; fm++) {
        const int r0 = rowBlk + mBase + fm * 16 + g;
        const int r1 = r0 + 8;
        #pragma unroll
        for (int fn = 0; fn < 4; fn++) {
            const int col = colBlk + nBase + fn * 8 + tg * 2;
            float c0 = acc[fm][fn][0] * alpha;
            float c1 = acc[fm][fn][1] * alpha;
            float c2 = acc[fm][fn][2] * alpha;
            float c3 = acc[fm][fn][3] * alpha;
            if (bias) {
                float b0 = bias[col], b1 = bias[col + 1];
                c0 += b0; c1 += b1; c2 += b0; c3 += b1;
            }
            if (!TSTORE) {
                *(float2*)(C + (long long)r0 * ldc + col) = make_float2(c0, c1);
                *(float2*)(C + (long long)r1 * ldc + col) = make_float2(c2, c3);
            } else {
                const long long n0 = r0 >> 11; const int s0 = r0 & 2047;
                const long long n1 = r1 >> 11; const int s1 = r1 & 2047;
                C[n0 * 2097152LL + (long long)(col    ) * 2048 + s0] = c0;
                C[n0 * 2097152LL + (long long)(col + 1) * 2048 + s0] = c1;
                C[n1 * 2097152LL + (long long)(col    ) * 2048 + s1] = c2;
                C[n1 * 2097152LL + (long long)(col + 1) * 2048 + s1] = c3;
            }
        }
    }
}

// ---------------------------------------------------------------------------
// Fused attention core: scores (tf32 MMA) + stable softmax + w write + PV.
// One CTA = 128 query rows of one head. 256 threads, 8 warps x 16 rows.
// Pass 1: online (rowmax, sum-exp) over 16 K-tiles.
// Pass 2: recompute scores (bit-identical), write w = exp(s-m)/S, PV-MMA.
// SMEM: Qs[128][68] | Ks[128][68] | Vs[64][132] | Ws[128][132]  (~167 KB)
// ---------------------------------------------------------------------------
__global__ __launch_bounds__(256)
void attn_fused(const float* __restrict__ Q, const float* __restrict__ Kp,
                const float* __restrict__ Vt, float* __restrict__ Wout,
                float* __restrict__ Aout)
{
    extern __shared__ float sm[];
    float* Qs = sm;              // 128*68
    float* Ks = sm + 8704;       // 128*68
    float* Vs = sm + 17408;      // 64*132
    float* Ws = sm + 25856;      // 128*132

    const int tid  = threadIdx.x;
    const int wid  = tid >> 5;
    const int lane = tid & 31;
    const int g    = lane >> 2;
    const int tg   = lane & 3;
    const int mBase = wid * 16;

    const int lb = blockIdx.x;            // L-block (0..15)
    const int z  = blockIdx.y;            // n*16+h (0..31)
    const int n  = z >> 4, h = z & 15;

    const float* Qz = Q  + (long long)n * (LQ * EDIM) + (long long)lb * 128 * EDIM + h * 64;
    const float* Kz = Kp + (long long)n * (SK * EDIM) + h * 64;
    const float* Vz = Vt + (long long)n * (EDIM * SK) + (long long)h * 64 * SK;
    float* Wz = Wout + ((long long)z * LQ + (long long)lb * 128) * SK;
    float* Az = Aout + (long long)n * (LQ * EDIM) + (long long)lb * 128 * EDIM + h * 64;

    // ---- load Q tile, pre-scaled by 1/8 (exact), tf32 ----
    #pragma unroll
    for (int i = 0; i < 8; i++) {
        int idx = i * 256 + tid;
        int r = idx >> 4, c = (idx & 15) << 2;
        float4 v = *(const float4*)(Qz + (long long)r * EDIM + c);
        Qs[r * 68 + c + 0] = __uint_as_float(f2tf32(v.x * 0.125f));
        Qs[r * 68 + c + 1] = __uint_as_float(f2tf32(v.y * 0.125f));
        Qs[r * 68 + c + 2] = __uint_as_float(f2tf32(v.z * 0.125f));
        Qs[r * 68 + c + 3] = __uint_as_float(f2tf32(v.w * 0.125f));
    }

    float m0 = -1e30f, m1 = -1e30f, s0 = 0.0f, s1 = 0.0f;

    // =================== pass 1: online max & sum ===================
    for (int t = 0; t < 16; t++) {
        #pragma unroll
        for (int i = 0; i < 8; i++) {
            int idx = i * 256 + tid;
            int r = idx >> 4, c = (idx & 15) << 2;
            float4 v = *(const float4*)(Kz + (long long)(t * 128 + r) * EDIM + c);
            Ks[r * 68 + c + 0] = __uint_as_float(f2tf32(v.x));
            Ks[r * 68 + c + 1] = __uint_as_float(f2tf32(v.y));
            Ks[r * 68 + c + 2] = __uint_as_float(f2tf32(v.z));
            Ks[r * 68 + c + 3] = __uint_as_float(f2tf32(v.w));
        }
        __syncthreads();

        float acc[16][4] = {};
        #pragma unroll
        for (int kk = 0; kk < 64; kk += 8) {
            uint32_t af[4];
            af[0] = __float_as_uint(Qs[(mBase + g    ) * 68 + kk + tg]);
            af[1] = __float_as_uint(Qs[(mBase + g + 8) * 68 + kk + tg]);
            af[2] = __float_as_uint(Qs[(mBase + g    ) * 68 + kk + tg + 4]);
            af[3] = __float_as_uint(Qs[(mBase + g + 8) * 68 + kk + tg + 4]);
            #pragma unroll
            for (int fn = 0; fn < 16; fn++) {
                uint32_t bf[2];
                bf[0] = __float_as_uint(Ks[(fn * 8 + g) * 68 + kk + tg]);
                bf[1] = __float_as_uint(Ks[(fn * 8 + g) * 68 + kk + tg + 4]);
                mma_tf32(acc[fn], af, bf);
            }
        }

        float t0 = -1e30f, t1 = -1e30f;
        #pragma unroll
        for (int fn = 0; fn < 16; fn++) {
            t0 = fmaxf(t0, fmaxf(acc[fn][0], acc[fn][1]));
            t1 = fmaxf(t1, fmaxf(acc[fn][2], acc[fn][3]));
        }
        t0 = fmaxf(t0, __shfl_xor_sync(0xffffffffu, t0, 1));
        t0 = fmaxf(t0, __shfl_xor_sync(0xffffffffu, t0, 2));
        t1 = fmaxf(t1, __shfl_xor_sync(0xffffffffu, t1, 1));
        t1 = fmaxf(t1, __shfl_xor_sync(0xffffffffu, t1, 2));
        const float m0n = fmaxf(m0, t0);
        const float m1n = fmaxf(m1, t1);

        float e0 = 0.0f, e1 = 0.0f;
        #pragma unroll
        for (int fn = 0; fn < 16; fn++) {
            e0 += __expf(acc[fn][0] - m0n) + __expf(acc[fn][1] - m0n);
            e1 += __expf(acc[fn][2] - m1n) + __expf(acc[fn][3] - m1n);
        }
        e0 += __shfl_xor_sync(0xffffffffu, e0, 1);
        e0 += __shfl_xor_sync(0xffffffffu, e0, 2);
        e1 += __shfl_xor_sync(0xffffffffu, e1, 1);
        e1 += __shfl_xor_sync(0xffffffffu, e1, 2);

        s0 = s0 * __expf(m0 - m0n) + e0;  m0 = m0n;
        s1 = s1 * __expf(m1 - m1n) + e1;  m1 = m1n;
        __syncthreads();
    }
    const float inv0 = 1.0f / s0;
    const float inv1 = 1.0f / s1;

    // =================== pass 2: w write + PV ===================
    float outA[8][4] = {};
    for (int t = 0; t < 16; t++) {
        #pragma unroll
        for (int i = 0; i < 8; i++) {
            int idx = i * 256 + tid;
            int r = idx >> 4, c = (idx & 15) << 2;
            float4 v = *(const float4*)(Kz + (long long)(t * 128 + r) * EDIM + c);
            Ks[r * 68 + c + 0] = __uint_as_float(f2tf32(v.x));
            Ks[r * 68 + c + 1] = __uint_as_float(f2tf32(v.y));
            Ks[r * 68 + c + 2] = __uint_as_float(f2tf32(v.z));
            Ks[r * 68 + c + 3] = __uint_as_float(f2tf32(v.w));
        }
        #pragma unroll
        for (int i = 0; i < 8; i++) {
            int idx = i * 256 + tid;
            int r = idx >> 5, c = (idx & 31) << 2;
            float4 v = *(const float4*)(Vz + (long long)r * SK + t * 128 + c);
            Vs[r * 132 + c + 0] = __uint_as_float(f2tf32(v.x));
            Vs[r * 132 + c + 1] = __uint_as_float(f2tf32(v.y));
            Vs[r * 132 + c + 2] = __uint_as_float(f2tf32(v.z));
            Vs[r * 132 + c + 3] = __uint_as_float(f2tf32(v.w));
        }
        __syncthreads();

        float acc[16][4] = {};
        #pragma unroll
        for (int kk = 0; kk < 64; kk += 8) {
            uint32_t af[4];
            af[0] = __float_as_uint(Qs[(mBase + g    ) * 68 + kk + tg]);
            af[1] = __float_as_uint(Qs[(mBase + g + 8) * 68 + kk + tg]);
            af[2] = __float_as_uint(Qs[(mBase + g    ) * 68 + kk + tg + 4]);
            af[3] = __float_as_uint(Qs[(mBase + g + 8) * 68 + kk + tg + 4]);
            #pragma unroll
            for (int fn = 0; fn < 16; fn++) {
                uint32_t bf[2];
                bf[0] = __float_as_uint(Ks[(fn * 8 + g) * 68 + kk + tg]);
                bf[1] = __float_as_uint(Ks[(fn * 8 + g) * 68 + kk + tg + 4]);
                mma_tf32(acc[fn], af, bf);
            }
        }

        // w values into Ws
        #pragma unroll
        for (int fn = 0; fn < 16; fn++) {
            float w0 = __expf(acc[fn][0] - m0) * inv0;
            float w1 = __expf(acc[fn][1] - m0) * inv0;
            float w2 = __expf(acc[fn][2] - m1) * inv1;
            float w3 = __expf(acc[fn][3] - m1) * inv1;
            *(float2*)(Ws + (mBase + g    ) * 132 + fn * 8 + tg * 2) = make_float2(w0, w1);
            *(float2*)(Ws + (mBase + g + 8) * 132 + fn * 8 + tg * 2) = make_float2(w2, w3);
        }
        __syncthreads();

        // coalesced w tile -> gmem (128 rows x 128 cols = 4096 float4, 16 iters)
        #pragma unroll
        for (int i = 0; i < 16; i++) {
            int idx = i * 256 + tid;
            int r = idx >> 5, c = (idx & 31) << 2;
            float4 v = *(const float4*)(Ws + r * 132 + c);
            *(float4*)(Wz + (long long)r * SK + t * 128 + c) = v;
        }

        // PV MMA: A = w tile (cvt tf32 from Ws), B = Vs
        #pragma unroll
        for (int kk = 0; kk < 128; kk += 8) {
            uint32_t af[4];
            af[0] = f2tf32(Ws[(mBase + g    ) * 132 + kk + tg]);
            af[1] = f2tf32(Ws[(mBase + g + 8) * 132 + kk + tg]);
            af[2] = f2tf32(Ws[(mBase + g    ) * 132 + kk + tg + 4]);
            af[3] = f2tf32(Ws[(mBase + g + 8) * 132 + kk + tg + 4]);
            #pragma unroll
            for (int fn = 0; fn < 8; fn++) {
                uint32_t bf[2];
                bf[0] = __float_as_uint(Vs[(fn * 8 + g) * 132 + kk + tg]);
                bf[1] = __float_as_uint(Vs[(fn * 8 + g) * 132 + kk + tg + 4]);
                mma_tf32(outA[fn], af, bf);
            }
        }
        __syncthreads();
    }

    // epilogue: attn output (N,L,E) at head offset
    #pragma unroll
    for (int fn = 0; fn < 8; fn++) {
        const int col = fn * 8 + tg * 2;
        const int r0 = mBase + g, r1 = r0 + 8;
        *(float2*)(Az + (long long)r0 * EDIM + col) = make_float2(outA[fn][0], outA[fn][1]);
        *(float2*)(Az + (long long)r1 * EDIM + col) = make_float2(outA[fn][2], outA[fn][3]);
    }
}

// ---------------------------------------------------------------------------
extern "C" void kernel_launch(void* const* d_in, const int* in_sizes, int n_in,
                              void* d_out, int out_size)
{
    const float* query = (const float*)d_in[0];
    const float* key   = (const float*)d_in[1];
    const float* value = (const float*)d_in[2];
    const float* Wq    = (const float*)d_in[3];
    const float* bq    = (const float*)d_in[4];
    const float* Wk    = (const float*)d_in[5];
    const float* bk    = (const float*)d_in[6];
    const float* Wv    = (const float*)d_in[7];
    const float* bv    = (const float*)d_in[8];
    const float* Wo    = (const float*)d_in[9];
    const float* bo    = (const float*)d_in[10];

    float* out = (float*)d_out;                   // (N, L, E)
    float* w   = out + (long long)NB * LQ * EDIM; // (N, H, L, S)

    float *pq, *pk, *pvT, *pa;
    cudaGetSymbolAddress((void**)&pq, g_q);
    cudaGetSymbolAddress((void**)&pk, g_k);
    cudaGetSymbolAddress((void**)&pvT, g_vT);
    cudaGetSymbolAddress((void**)&pa, g_attn);

    const int FUSED_SMEM = (8704 + 8704 + 8448 + 16896) * 4;  // 171008 B
    cudaFuncSetAttribute(attn_fused,
                         cudaFuncAttributeMaxDynamicSharedMemorySize, FUSED_SMEM);

    dim3 blk(256);
    dim3 gproj(EDIM / 128, (NB * LQ) / 128, 1);

    // Q/K projections (NT GEMM), V projection with transposed store
    gemm_mma<128, false><<<gproj, blk>>>(
        query, Wq, pq, bq, EDIM, EDIM, EDIM, EDIM, 1.0f);
    gemm_mma<128, false><<<gproj, blk>>>(
        key, Wk, pk, bk, EDIM, EDIM, EDIM, EDIM, 1.0f);
    gemm_mma<128, true><<<gproj, blk>>>(
        value, Wv, pvT, bv, EDIM, EDIM, EDIM, 0, 1.0f);

    // fused scores + softmax (+implicit L1 renorm) + w write + PV
    attn_fused<<<dim3(LQ / 128, NB * NH), blk, FUSED_SMEM>>>(pq, pk, pvT, w, pa);

    // output projection
    gemm_mma<128, false><<<gproj, blk>>>(
        pa, Wo, out, bo, EDIM, EDIM, EDIM, EDIM, 1.0f);
}

// round 9
// speedup vs baseline: 4.2240x; 1.0134x over previous
#include <cuda_runtime.h>
#include <cstdint>
#include <math.h>

#define EDIM 1024
#define NH   16
#define HD   64
#define NB   2
#define LQ   2048
#define SK   2048

// Scratch (device globals = allocation-rule-safe scratch)
__device__ float g_q[NB * LQ * EDIM];       // Q projected (N,L,E)
__device__ float g_k[NB * SK * EDIM];       // K projected (N,S,E)
__device__ float g_vT[NB * NH * HD * SK];   // V projected, transposed (N,H,D,S)
__device__ float g_attn[NB * LQ * EDIM];    // attn out (N,L,E)

__device__ __forceinline__ uint32_t f2tf32(float f) {
    uint32_t u;
    asm("cvt.rna.tf32.f32 %0, %1;" : "=r"(u) : "f"(f));
    return u;
}
__device__ __forceinline__ float tf32f(float f) {
    return __uint_as_float(f2tf32(f));
}
__device__ __forceinline__ uint32_t smem_u32(const void* p) {
    uint32_t a;
    asm("{ .reg .u64 t; cvta.to.shared.u64 t, %1; cvt.u32.u64 %0, t; }"
        : "=r"(a) : "l"(p));
    return a;
}
__device__ __forceinline__ void mma_tf32(float* c, const uint32_t* a, const uint32_t* b) {
    asm volatile(
        "mma.sync.aligned.m16n8k8.row.col.f32.tf32.tf32.f32 "
        "{%0,%1,%2,%3}, {%4,%5,%6,%7}, {%8,%9}, {%0,%1,%2,%3};"
        : "+f"(c[0]), "+f"(c[1]), "+f"(c[2]), "+f"(c[3])
        : "r"(a[0]), "r"(a[1]), "r"(a[2]), "r"(a[3]), "r"(b[0]), "r"(b[1]));
}
#define CP_ASYNC(s, g) \
    asm volatile("cp.async.cg.shared.global [%0], [%1], 16;" :: "r"(s), "l"(g) : "memory")
#define CP_COMMIT() asm volatile("cp.async.commit_group;" ::: "memory")
#define CP_WAIT1()  asm volatile("cp.async.wait_group 1;" ::: "memory")

// ---------------------------------------------------------------------------
// Projection GEMM body: C[4096,1024] = A[4096,1024] @ B[1024,1024]^T + bias
// 128x128 CTA tile, BK=16, 256 threads, double-buffered, tf32 mma.sync.
// tstore: write output transposed into (N,H,D,S) layout (V projection).
// ---------------------------------------------------------------------------
__device__ __forceinline__ void proj_body(
    const float* __restrict__ A, const float* __restrict__ B,
    float* __restrict__ C, const float* __restrict__ bias, bool tstore)
{
    __shared__ float As[2][128][20];
    __shared__ float Bs[2][128][20];

    const int tid  = threadIdx.x;
    const int wid  = tid >> 5;
    const int lane = tid & 31;
    const int g    = lane >> 2;
    const int tg   = lane & 3;
    const int wm   = wid & 1;
    const int wn   = wid >> 1;
    const int mBase = wm * 64;
    const int nBase = wn * 32;

    const float* Az = A + (long long)(blockIdx.y * 128) * EDIM;
    const float* Bz = B + (long long)(blockIdx.x * 128) * EDIM;

    uint32_t ra[2][4], rb[2][4];

    #pragma unroll
    for (int i = 0; i < 2; i++) {
        int idx = i * 256 + tid;
        int r = idx >> 2, c = (idx & 3) << 2;
        float4 v = *(const float4*)(Az + (long long)r * EDIM + c);
        As[0][r][c + 0] = tf32f(v.x); As[0][r][c + 1] = tf32f(v.y);
        As[0][r][c + 2] = tf32f(v.z); As[0][r][c + 3] = tf32f(v.w);
        float4 w = *(const float4*)(Bz + (long long)r * EDIM + c);
        Bs[0][r][c + 0] = tf32f(w.x); Bs[0][r][c + 1] = tf32f(w.y);
        Bs[0][r][c + 2] = tf32f(w.z); Bs[0][r][c + 3] = tf32f(w.w);
    }
    __syncthreads();

    float acc[4][4][4] = {};
    int cur = 0;

    for (int t = 0; t < 64; t++) {
        if (t + 1 < 64) {
            const int k0 = (t + 1) << 4;
            #pragma unroll
            for (int i = 0; i < 2; i++) {
                int idx = i * 256 + tid;
                int r = idx >> 2, c = (idx & 3) << 2;
                float4 v = *(const float4*)(Az + (long long)r * EDIM + k0 + c);
                ra[i][0] = f2tf32(v.x); ra[i][1] = f2tf32(v.y);
                ra[i][2] = f2tf32(v.z); ra[i][3] = f2tf32(v.w);
                float4 w = *(const float4*)(Bz + (long long)r * EDIM + k0 + c);
                rb[i][0] = f2tf32(w.x); rb[i][1] = f2tf32(w.y);
                rb[i][2] = f2tf32(w.z); rb[i][3] = f2tf32(w.w);
            }
        }
        #pragma unroll
        for (int ks = 0; ks < 2; ks++) {
            const int kk = ks * 8;
            uint32_t af[4][4];
            #pragma unroll
            for (int fm = 0; fm < 4; fm++) {
                const int r = mBase + fm * 16 + g;
                af[fm][0] = __float_as_uint(As[cur][r    ][kk + tg]);
                af[fm][1] = __float_as_uint(As[cur][r + 8][kk + tg]);
                af[fm][2] = __float_as_uint(As[cur][r    ][kk + tg + 4]);
                af[fm][3] = __float_as_uint(As[cur][r + 8][kk + tg + 4]);
            }
            uint32_t bf[4][2];
            #pragma unroll
            for (int fn = 0; fn < 4; fn++) {
                const int r = nBase + fn * 8 + g;
                bf[fn][0] = __float_as_uint(Bs[cur][r][kk + tg]);
                bf[fn][1] = __float_as_uint(Bs[cur][r][kk + tg + 4]);
            }
            #pragma unroll
            for (int fm = 0; fm < 4; fm++)
                #pragma unroll
                for (int fn = 0; fn < 4; fn++)
                    mma_tf32(acc[fm][fn], af[fm], bf[fn]);
        }
        if (t + 1 < 64) {
            const int nxt = cur ^ 1;
            #pragma unroll
            for (int i = 0; i < 2; i++) {
                int idx = i * 256 + tid;
                int r = idx >> 2, c = (idx & 3) << 2;
                As[nxt][r][c + 0] = __uint_as_float(ra[i][0]);
                As[nxt][r][c + 1] = __uint_as_float(ra[i][1]);
                As[nxt][r][c + 2] = __uint_as_float(ra[i][2]);
                As[nxt][r][c + 3] = __uint_as_float(ra[i][3]);
                Bs[nxt][r][c + 0] = __uint_as_float(rb[i][0]);
                Bs[nxt][r][c + 1] = __uint_as_float(rb[i][1]);
                Bs[nxt][r][c + 2] = __uint_as_float(rb[i][2]);
                Bs[nxt][r][c + 3] = __uint_as_float(rb[i][3]);
            }
            __syncthreads();
            cur = nxt;
        }
    }

    const int rowBlk = blockIdx.y * 128;
    const int colBlk = blockIdx.x * 128;
    #pragma unroll
    for (int fm = 0; fm < 4; fm++) {
        const int r0 = rowBlk + mBase + fm * 16 + g;
        const int r1 = r0 + 8;
        #pragma unroll
        for (int fn = 0; fn < 4; fn++) {
            const int col = colBlk + nBase + fn * 8 + tg * 2;
            float b0 = bias[col], b1 = bias[col + 1];
            float c0 = acc[fm][fn][0] + b0;
            float c1 = acc[fm][fn][1] + b1;
            float c2 = acc[fm][fn][2] + b0;
            float c3 = acc[fm][fn][3] + b1;
            if (!tstore) {
                *(float2*)(C + (long long)r0 * EDIM + col) = make_float2(c0, c1);
                *(float2*)(C + (long long)r1 * EDIM + col) = make_float2(c2, c3);
            } else {
                const long long n0 = r0 >> 11; const int s0 = r0 & 2047;
                const long long n1 = r1 >> 11; const int s1 = r1 & 2047;
                C[n0 * 2097152LL + (long long)(col    ) * 2048 + s0] = c0;
                C[n0 * 2097152LL + (long long)(col + 1) * 2048 + s0] = c1;
                C[n1 * 2097152LL + (long long)(col    ) * 2048 + s1] = c2;
                C[n1 * 2097152LL + (long long)(col + 1) * 2048 + s1] = c3;
            }
        }
    }
}

__global__ __launch_bounds__(256, 2) void qkv_proj(
    const float* __restrict__ q, const float* __restrict__ k, const float* __restrict__ v,
    const float* __restrict__ Wq, const float* __restrict__ bq,
    const float* __restrict__ Wk, const float* __restrict__ bk,
    const float* __restrict__ Wv, const float* __restrict__ bv,
    float* __restrict__ pq, float* __restrict__ pk, float* __restrict__ pvT)
{
    const int z = blockIdx.z;
    const float* A    = (z == 0) ? q  : (z == 1) ? k  : v;
    const float* B    = (z == 0) ? Wq : (z == 1) ? Wk : Wv;
    const float* bias = (z == 0) ? bq : (z == 1) ? bk : bv;
    float*       C    = (z == 0) ? pq : (z == 1) ? pk : pvT;
    proj_body(A, B, C, bias, z == 2);
}

__global__ __launch_bounds__(256, 2) void o_proj(
    const float* __restrict__ A, const float* __restrict__ B,
    float* __restrict__ C, const float* __restrict__ bias)
{
    proj_body(A, B, C, bias, false);
}

// ---------------------------------------------------------------------------
// Fused attention: scores + softmax + w write + PV, cp.async 3-stage pipeline.
// One CTA = 128 query rows of one head; 256 threads (8 warps x 16 rows).
// K rows permuted within 8-groups (pi = [0,4,1,5,2,6,3,7]) so the scores
// C-fragment is directly the PV A-fragment.  Q held in registers.
// SMEM: K ring 3x128x68 + V ring 3x64x132 = 205824 B.
// ---------------------------------------------------------------------------
__global__ __launch_bounds__(256)
void attn_fused(const float* __restrict__ Q, const float* __restrict__ Kp,
                const float* __restrict__ Vt, float* __restrict__ Wout,
                float* __restrict__ Aout)
{
    extern __shared__ float sm[];
    float* KsB = sm;            // 3 x 8704
    float* VsB = sm + 26112;    // 3 x 8448
    const uint32_t ksu = smem_u32(sm);
    const uint32_t vsu = ksu + 26112u * 4u;

    const int tid  = threadIdx.x;
    const int wid  = tid >> 5;
    const int lane = tid & 31;
    const int g    = lane >> 2;
    const int tg   = lane & 3;
    const int mBase = wid * 16;

    const int lb = blockIdx.x;
    const int z  = blockIdx.y;
    const int n  = z >> 4, h = z & 15;

    const float* Qz = Q  + (long long)n * (LQ * EDIM) + (long long)lb * 128 * EDIM + h * 64;
    const float* Kz = Kp + (long long)n * (SK * EDIM) + h * 64;
    const float* Vz = Vt + (long long)n * ((long long)EDIM * SK) + (long long)h * 64 * SK;
    float* Wz = Wout + ((long long)z * LQ + (long long)lb * 128) * SK;
    float* Az = Aout + (long long)n * (LQ * EDIM) + (long long)lb * 128 * EDIM + h * 64;

    // ---- stage Q through K slot 0 (scaled by 1/8, tf32), then into regs ----
    #pragma unroll
    for (int i = 0; i < 8; i++) {
        int idx = i * 256 + tid;
        int r = idx >> 4, c = (idx & 15) << 2;
        float4 v = *(const float4*)(Qz + (long long)r * EDIM + c);
        KsB[r * 68 + c + 0] = tf32f(v.x * 0.125f);
        KsB[r * 68 + c + 1] = tf32f(v.y * 0.125f);
        KsB[r * 68 + c + 2] = tf32f(v.z * 0.125f);
        KsB[r * 68 + c + 3] = tf32f(v.w * 0.125f);
    }
    __syncthreads();
    uint32_t qa[8][4];
    #pragma unroll
    for (int kc = 0; kc < 8; kc++) {
        qa[kc][0] = __float_as_uint(KsB[(mBase + g    ) * 68 + kc * 8 + tg]);
        qa[kc][1] = __float_as_uint(KsB[(mBase + g + 8) * 68 + kc * 8 + tg]);
        qa[kc][2] = __float_as_uint(KsB[(mBase + g    ) * 68 + kc * 8 + tg + 4]);
        qa[kc][3] = __float_as_uint(KsB[(mBase + g + 8) * 68 + kc * 8 + tg + 4]);
    }
    __syncthreads();

    auto issueK = [&](int t) {
        const int slot = t % 3;
        #pragma unroll
        for (int i = 0; i < 8; i++) {
            int c = i * 256 + tid;
            int row = c >> 4, cc = (c & 15) << 2;
            int srow = (row & ~7) | (((row & 6) >> 1) | ((row & 1) << 2));  // pi
            CP_ASYNC(ksu + (uint32_t)(slot * 8704 + row * 68 + cc) * 4u,
                     Kz + (long long)(t * 128 + srow) * EDIM + cc);
        }
    };
    auto issueV = [&](int t) {
        const int slot = t % 3;
        #pragma unroll
        for (int i = 0; i < 8; i++) {
            int c = i * 256 + tid;
            int row = c >> 5, cc = (c & 31) << 2;
            CP_ASYNC(vsu + (uint32_t)(slot * 8448 + row * 132 + cc) * 4u,
                     Vz + (long long)row * SK + t * 128 + cc);
        }
    };
    auto cvtK = [&](int slot) {
        #pragma unroll
        for (int i = 0; i < 8; i++) {
            int c = i * 256 + tid;
            int row = c >> 4, cc = (c & 15) << 2;
            float4* p = (float4*)(KsB + slot * 8704 + row * 68 + cc);
            float4 v = *p;
            v.x = tf32f(v.x); v.y = tf32f(v.y); v.z = tf32f(v.z); v.w = tf32f(v.w);
            *p = v;
        }
    };
    auto cvtV = [&](int slot) {
        #pragma unroll
        for (int i = 0; i < 8; i++) {
            int c = i * 256 + tid;
            int row = c >> 5, cc = (c & 31) << 2;
            float4* p = (float4*)(VsB + slot * 8448 + row * 132 + cc);
            float4 v = *p;
            v.x = tf32f(v.x); v.y = tf32f(v.y); v.z = tf32f(v.z); v.w = tf32f(v.w);
            *p = v;
        }
    };

    // =================== pass 1: online max & sum-exp ===================
    issueK(0); CP_COMMIT();
    issueK(1); CP_COMMIT();
    float m0 = -1e30f, m1 = -1e30f, s0 = 0.0f, s1 = 0.0f;

    for (int t = 0; t < 16; t++) {
        CP_WAIT1();
        __syncthreads();
        cvtK(t % 3);
        if (t + 2 < 16) issueK(t + 2);
        CP_COMMIT();
        __syncthreads();

        const float* kb = KsB + (t % 3) * 8704;
        float acc[16][4] = {};
        #pragma unroll
        for (int kc = 0; kc < 8; kc++) {
            #pragma unroll
            for (int fn = 0; fn < 16; fn++) {
                uint32_t bf[2];
                bf[0] = __float_as_uint(kb[(fn * 8 + g) * 68 + kc * 8 + tg]);
                bf[1] = __float_as_uint(kb[(fn * 8 + g) * 68 + kc * 8 + tg + 4]);
                mma_tf32(acc[fn], qa[kc], bf);
            }
        }

        float t0 = -1e30f, t1 = -1e30f;
        #pragma unroll
        for (int fn = 0; fn < 16; fn++) {
            t0 = fmaxf(t0, fmaxf(acc[fn][0], acc[fn][1]));
            t1 = fmaxf(t1, fmaxf(acc[fn][2], acc[fn][3]));
        }
        t0 = fmaxf(t0, __shfl_xor_sync(0xffffffffu, t0, 1));
        t0 = fmaxf(t0, __shfl_xor_sync(0xffffffffu, t0, 2));
        t1 = fmaxf(t1, __shfl_xor_sync(0xffffffffu, t1, 1));
        t1 = fmaxf(t1, __shfl_xor_sync(0xffffffffu, t1, 2));
        const float m0n = fmaxf(m0, t0);
        const float m1n = fmaxf(m1, t1);

        float e0 = 0.0f, e1 = 0.0f;
        #pragma unroll
        for (int fn = 0; fn < 16; fn++) {
            e0 += __expf(acc[fn][0] - m0n) + __expf(acc[fn][1] - m0n);
            e1 += __expf(acc[fn][2] - m1n) + __expf(acc[fn][3] - m1n);
        }
        e0 += __shfl_xor_sync(0xffffffffu, e0, 1);
        e0 += __shfl_xor_sync(0xffffffffu, e0, 2);
        e1 += __shfl_xor_sync(0xffffffffu, e1, 1);
        e1 += __shfl_xor_sync(0xffffffffu, e1, 2);

        s0 = s0 * __expf(m0 - m0n) + e0;  m0 = m0n;
        s1 = s1 * __expf(m1 - m1n) + e1;  m1 = m1n;
    }
    const float inv0 = 1.0f / s0;
    const float inv1 = 1.0f / s1;
    __syncthreads();   // all warps done with K slot 0 (tile 15) before reissue

    // =================== pass 2: w write + PV ===================
    issueK(0); issueV(0); CP_COMMIT();
    issueK(1); issueV(1); CP_COMMIT();
    float outA[8][4] = {};

    for (int t = 0; t < 16; t++) {
        CP_WAIT1();
        __syncthreads();
        cvtK(t % 3);
        cvtV(t % 3);
        if (t + 2 < 16) { issueK(t + 2); issueV(t + 2); }
        CP_COMMIT();
        __syncthreads();

        const float* kb = KsB + (t % 3) * 8704;
        const float* vb = VsB + (t % 3) * 8448;

        float acc[16][4] = {};
        #pragma unroll
        for (int kc = 0; kc < 8; kc++) {
            #pragma unroll
            for (int fn = 0; fn < 16; fn++) {
                uint32_t bf[2];
                bf[0] = __float_as_uint(kb[(fn * 8 + g) * 68 + kc * 8 + tg]);
                bf[1] = __float_as_uint(kb[(fn * 8 + g) * 68 + kc * 8 + tg + 4]);
                mma_tf32(acc[fn], qa[kc], bf);
            }
        }

        // exp + direct w store + PV (scores frag == PV A frag thanks to pi)
        #pragma unroll
        for (int fn = 0; fn < 16; fn++) {
            float w0 = __expf(acc[fn][0] - m0) * inv0;
            float w1 = __expf(acc[fn][1] - m0) * inv0;
            float w2 = __expf(acc[fn][2] - m1) * inv1;
            float w3 = __expf(acc[fn][3] - m1) * inv1;
            float* wr0 = Wz + (long long)(mBase + g    ) * SK + t * 128 + fn * 8;
            float* wr1 = Wz + (long long)(mBase + g + 8) * SK + t * 128 + fn * 8;
            wr0[tg] = w0; wr0[tg + 4] = w1;
            wr1[tg] = w2; wr1[tg + 4] = w3;
            uint32_t af[4];
            af[0] = f2tf32(w0); af[1] = f2tf32(w2);
            af[2] = f2tf32(w1); af[3] = f2tf32(w3);
            #pragma unroll
            for (int fn2 = 0; fn2 < 8; fn2++) {
                uint32_t bf[2];
                bf[0] = __float_as_uint(vb[(fn2 * 8 + g) * 132 + fn * 8 + tg]);
                bf[1] = __float_as_uint(vb[(fn2 * 8 + g) * 132 + fn * 8 + tg + 4]);
                mma_tf32(outA[fn2], af, bf);
            }
        }
    }

    // epilogue: attn output (N,L,E) at head offset
    #pragma unroll
    for (int fn = 0; fn < 8; fn++) {
        const int col = fn * 8 + tg * 2;
        *(float2*)(Az + (long long)(mBase + g    ) * EDIM + col) =
            make_float2(outA[fn][0], outA[fn][1]);
        *(float2*)(Az + (long long)(mBase + g + 8) * EDIM + col) =
            make_float2(outA[fn][2], outA[fn][3]);
    }
}

// ---------------------------------------------------------------------------
extern "C" void kernel_launch(void* const* d_in, const int* in_sizes, int n_in,
                              void* d_out, int out_size)
{
    const float* query = (const float*)d_in[0];
    const float* key   = (const float*)d_in[1];
    const float* value = (const float*)d_in[2];
    const float* Wq    = (const float*)d_in[3];
    const float* bq    = (const float*)d_in[4];
    const float* Wk    = (const float*)d_in[5];
    const float* bk    = (const float*)d_in[6];
    const float* Wv    = (const float*)d_in[7];
    const float* bv    = (const float*)d_in[8];
    const float* Wo    = (const float*)d_in[9];
    const float* bo    = (const float*)d_in[10];

    float* out = (float*)d_out;                   // (N, L, E)
    float* w   = out + (long long)NB * LQ * EDIM; // (N, H, L, S)

    float *pq, *pk, *pvT, *pa;
    cudaGetSymbolAddress((void**)&pq, g_q);
    cudaGetSymbolAddress((void**)&pk, g_k);
    cudaGetSymbolAddress((void**)&pvT, g_vT);
    cudaGetSymbolAddress((void**)&pa, g_attn);

    const int ASMEM = (3 * 8704 + 3 * 8448) * 4;  // 205824 B
    cudaFuncSetAttribute(attn_fused,
                         cudaFuncAttributeMaxDynamicSharedMemorySize, ASMEM);

    // fused Q/K/V projections (one launch, grid.z selects)
    qkv_proj<<<dim3(8, 32, 3), 256>>>(query, key, value,
                                      Wq, bq, Wk, bk, Wv, bv,
                                      pq, pk, pvT);

    // fused scores + softmax + w write + PV
    attn_fused<<<dim3(LQ / 128, NB * NH), 256, ASMEM>>>(pq, pk, pvT, w, pa);

    // output projection
    o_proj<<<dim3(8, 32), 256>>>(pa, Wo, out, bo);
}